// round 12
// baseline (speedup 1.0000x reference)
#include <cuda_runtime.h>
#include <cuda_bf16.h>
#include <cstdint>
#include <math.h>

#define NN 50000
#define NE 800000
#define TT 12
#define NPB 128
#define THREADS 128
#define SCAN_BLOCKS 196   // ceil(50000/256)

// ---------------- device scratch (no allocations) ----------------
__device__ int   g_cnt[NN];
__device__ int   g_off[NN];
__device__ int   g_fill[NN];
__device__ int   g_srcs[NE];
__device__ float g_dinv[NN];
__device__ float g_agg[NN * 24];    // raw: sum_e dinv[src]*x[src][c]
__device__ int   g_bsum[256];
__device__ int   g_bpre[256];
__device__ int   g_is64;

// ---------------- preprocessing: CSR build + gather ----------------
__global__ void k_initprobe(const int* __restrict__ ei32) {
    int i = blockIdx.x * blockDim.x + threadIdx.x;
    int stride = gridDim.x * blockDim.x;
    for (int j = i; j < NN; j += stride) g_cnt[j] = 0;
    if (blockIdx.x == 0) {
        int nz = 0;
        for (int j = threadIdx.x; j < 1024; j += blockDim.x)
            if (ei32[2 * j + 1] != 0) nz = 1;
        int any = __syncthreads_or(nz);
        if (threadIdx.x == 0) g_is64 = any ? 0 : 1;
    }
}

__device__ __forceinline__ void load_edge(const int* ei32, int e, int& s, int& d) {
    if (g_is64) { s = ei32[2 * e]; d = ei32[2 * (NE + e)]; }
    else        { s = ei32[e];     d = ei32[NE + e]; }
}

__global__ void k_count(const int* __restrict__ ei32) {
    int e = blockIdx.x * blockDim.x + threadIdx.x;
    if (e >= NE) return;
    int s, d;
    load_edge(ei32, e, s, d);
    atomicAdd(&g_cnt[d], 1);
}

__global__ void k_scan1() {
    __shared__ int sc[256];
    int tid = threadIdx.x;
    int i = blockIdx.x * 256 + tid;
    int v = (i < NN) ? g_cnt[i] : 0;
    sc[tid] = v;
    __syncthreads();
#pragma unroll
    for (int ofs = 1; ofs < 256; ofs <<= 1) {
        int t = (tid >= ofs) ? sc[tid - ofs] : 0;
        __syncthreads();
        sc[tid] += t;
        __syncthreads();
    }
    if (i < NN) g_off[i] = sc[tid] - v;
    if (tid == 255) g_bsum[blockIdx.x] = sc[255];
}

__global__ void k_scan2() {
    __shared__ int sc[256];
    int tid = threadIdx.x;
    int v = (tid < SCAN_BLOCKS) ? g_bsum[tid] : 0;
    sc[tid] = v;
    __syncthreads();
#pragma unroll
    for (int ofs = 1; ofs < 256; ofs <<= 1) {
        int t = (tid >= ofs) ? sc[tid - ofs] : 0;
        __syncthreads();
        sc[tid] += t;
        __syncthreads();
    }
    g_bpre[tid] = sc[tid] - v;
}

__global__ void k_scan3() {
    int i = blockIdx.x * 256 + threadIdx.x;
    if (i >= NN) return;
    int off = g_off[i] + g_bpre[blockIdx.x];
    g_off[i]  = off;
    g_fill[i] = off;
    g_dinv[i] = rsqrtf((float)g_cnt[i] + 1.0f);
}

__global__ void k_fill(const int* __restrict__ ei32) {
    int e = blockIdx.x * blockDim.x + threadIdx.x;
    if (e >= NE) return;
    int s, d;
    load_edge(ei32, e, s, d);
    int pos = atomicAdd(&g_fill[d], 1);
    g_srcs[pos] = s;
}

__global__ void k_gather(const float* __restrict__ x) {
    int w = (blockIdx.x * blockDim.x + threadIdx.x) >> 5;
    int lane = threadIdx.x & 31;
    if (w >= NN || lane >= 24) return;
    int start = g_off[w];
    int end = (w + 1 < NN) ? g_off[w + 1] : NE;
    float acc = 0.0f;
    for (int e = start; e < end; e++) {
        int s = g_srcs[e];
        acc = fmaf(g_dinv[s], __ldg(x + (size_t)s * 24 + lane), acc);
    }
    g_agg[(size_t)w * 24 + lane] = acc;
}

// ---------------- fast math (MUFU-based) ----------------
__device__ __forceinline__ float fsigmoid(float x) {
    float e, r;
    asm("ex2.approx.ftz.f32 %0, %1;" : "=f"(e) : "f"(-x * 1.4426950408889634f));
    asm("rcp.approx.ftz.f32 %0, %1;" : "=f"(r) : "f"(1.0f + e));
    return r;
}
__device__ __forceinline__ float ftanh(float x) {
    float r;
    asm("tanh.approx.f32 %0, %1;" : "=f"(r) : "f"(x));
    return r;
}

// ---------------- bf16 helpers ----------------
__device__ __forceinline__ float fhi(float x) {
    return __bfloat162float(__float2bfloat16_rn(x));
}
__device__ __forceinline__ uint32_t pk(float a, float b) {
    __nv_bfloat162 t = __floats2bfloat162_rn(a, b);
    return *reinterpret_cast<uint32_t*>(&t);
}
__device__ __forceinline__ float2 upk(uint32_t u) {
    __nv_bfloat162 t = *reinterpret_cast<__nv_bfloat162*>(&u);
    return make_float2(__low2float(t), __high2float(t));
}

// m16n8k16 row.col bf16 MMA, fp32 accumulate
__device__ __forceinline__ void mma16816(float* d, const uint32_t* a,
                                         uint32_t b0, uint32_t b1) {
    asm volatile(
        "mma.sync.aligned.m16n8k16.row.col.f32.bf16.bf16.f32 "
        "{%0,%1,%2,%3}, {%4,%5,%6,%7}, {%8,%9}, {%0,%1,%2,%3};"
        : "+f"(d[0]), "+f"(d[1]), "+f"(d[2]), "+f"(d[3])
        : "r"(a[0]), "r"(a[1]), "r"(a[2]), "r"(a[3]), "r"(b0), "r"(b1));
}

// ---------------- smem layout (bytes) ----------------
#define SM_B1    0          // 128 frags x 32 lanes x 16B = 64KB (rz: K=128,N=128)
#define SM_B2    65536      // 16KB (Wih_n: K=64,N=64)
#define SM_B3    81920      // 16KB (Whh_n)
#define SM_XA    98304      // float2[12][128] = 12KB
#define SM_WG3   110592     // float4[64] : {wg0, wg1, bg, 0}
#define SM_BIAS  111616     // float4[64] : {br, bz, bin, bhn}
#define SM_WFC   112640     // float[64]
#define SM_TOTAL 112896     // 2 CTAs per SM

// 4 warps x 32 nodes each; every B LDS.128 feeds 6 HMMAs (2 A-sets x 3 terms)
__global__ void __launch_bounds__(THREADS, 2)
k_fused(const float* __restrict__ x,
        const float* __restrict__ W_gcn, const float* __restrict__ b_gcn,
        const float* __restrict__ W_ih,  const float* __restrict__ W_hh,
        const float* __restrict__ b_ih,  const float* __restrict__ b_hh,
        const float* __restrict__ W_fc,  const float* __restrict__ b_fc,
        float* __restrict__ out) {
    extern __shared__ char smem[];
    const int tid  = threadIdx.x;
    const int wid  = tid >> 5;          // 0..3
    const int lane = tid & 31;
    const int gid  = lane >> 2;
    const int tig  = lane & 3;
    const int node0 = blockIdx.x * NPB;
    const int n0 = wid * 32 + gid;      // rows n0, n0+8 (set0); n0+16, n0+24 (set1)

    // ---- build B fragments (hi/lo interleaved, fragment-major) ----
    for (int i = tid; i < 6144; i += THREADS) {
        int f, l;
        const float* Wrow;
        int k0;
        uint32_t dst;
        if (i < 4096) {                       // B1: rz, 8kt x 16nt
            f = i >> 5; l = i & 31;
            int kt = f >> 4, nt = f & 15;
            int g = l >> 2, tg = l & 3;
            int j = 8 * nt + g;
            k0 = 16 * kt + 2 * tg;
            Wrow = (kt < 4) ? (W_ih + j * 64 + k0) : (W_hh + j * 64 + (k0 - 64));
            dst = SM_B1 + (uint32_t)(f * 32 + l) * 16;
        } else if (i < 5120) {                // B2: Wih_n
            int ii = i - 4096;
            f = ii >> 5; l = ii & 31;
            int kt = f >> 3, nt = f & 7;
            int g = l >> 2, tg = l & 3;
            int j = 8 * nt + g;
            k0 = 16 * kt + 2 * tg;
            Wrow = W_ih + (128 + j) * 64 + k0;
            dst = SM_B2 + (uint32_t)(f * 32 + l) * 16;
        } else {                              // B3: Whh_n
            int ii = i - 5120;
            f = ii >> 5; l = ii & 31;
            int kt = f >> 3, nt = f & 7;
            int g = l >> 2, tg = l & 3;
            int j = 8 * nt + g;
            k0 = 16 * kt + 2 * tg;
            Wrow = W_hh + (128 + j) * 64 + k0;
            dst = SM_B3 + (uint32_t)(f * 32 + l) * 16;
        }
        float w0 = Wrow[0], w1 = Wrow[1], w8 = Wrow[8], w9 = Wrow[9];
        float h0 = fhi(w0), h1 = fhi(w1), h8 = fhi(w8), h9 = fhi(w9);
        uint4 v;
        v.x = pk(h0, h1);
        v.y = pk(h8, h9);
        v.z = pk(w0 - h0, w1 - h1);
        v.w = pk(w8 - h8, w9 - h9);
        *(uint4*)(smem + dst) = v;
    }

    // ---- XA: dinv*(agg_raw + dinv*x), layout float2[t][n] ----
    float* sXA = (float*)(smem + SM_XA);
    for (int i = tid; i < NPB * 24; i += THREADS) {
        int n = i / 24, cc = i - n * 24;
        int t = cc >> 1, c = cc & 1;
        int node = node0 + n;
        float v = 0.0f;
        if (node < NN) {
            float dv = g_dinv[node];
            v = dv * (g_agg[(size_t)node * 24 + cc] + dv * x[(size_t)node * 24 + cc]);
        }
        sXA[(t * 128 + n) * 2 + c] = v;
    }
    if (tid < 64) {
        float4* wg3 = (float4*)(smem + SM_WG3);
        wg3[tid] = make_float4(W_gcn[tid], W_gcn[64 + tid], b_gcn[tid], 0.0f);
        float4* bia = (float4*)(smem + SM_BIAS);
        bia[tid] = make_float4(b_ih[tid] + b_hh[tid],
                               b_ih[64 + tid] + b_hh[64 + tid],
                               b_ih[128 + tid], b_hh[128 + tid]);
        ((float*)(smem + SM_WFC))[tid] = W_fc[tid];
    }
    __syncthreads();

    const float4* sWG3  = (const float4*)(smem + SM_WG3);
    const float4* sBIAS = (const float4*)(smem + SM_BIAS);
    const float*  sWFC  = (const float*)(smem + SM_WFC);

    // ---- hidden state packed bf16 hi/lo; [kt][0..3]=set0, [kt][4..7]=set1 ----
    uint32_t hh[4][8], hl[4][8];
#pragma unroll
    for (int kt = 0; kt < 4; kt++)
#pragma unroll
        for (int q = 0; q < 8; q++) { hh[kt][q] = 0u; hl[kt][q] = 0u; }

#pragma unroll 1
    for (int t = 0; t < TT; t++) {
        float2 xaA = *(const float2*)(sXA + (t * 128 + n0) * 2);
        float2 xaB = *(const float2*)(sXA + (t * 128 + n0 + 8) * 2);
        float2 xaC = *(const float2*)(sXA + (t * 128 + n0 + 16) * 2);
        float2 xaD = *(const float2*)(sXA + (t * 128 + n0 + 24) * 2);

        // ---- S fragments, 2 sets ----
        uint32_t sfH[4][8], sfL[4][8];
#pragma unroll
        for (int kt = 0; kt < 4; kt++) {
            int k0 = 16 * kt + 2 * tig;
            float4 g0 = sWG3[k0], g1 = sWG3[k0 + 1];
            float4 g8 = sWG3[k0 + 8], g9 = sWG3[k0 + 9];
#pragma unroll
            for (int st = 0; st < 2; st++) {
                float2 xA = st ? xaC : xaA;
                float2 xB = st ? xaD : xaB;
                float s00 = fmaxf(fmaf(xA.x, g0.x, fmaf(xA.y, g0.y, g0.z)), 0.0f);
                float s01 = fmaxf(fmaf(xA.x, g1.x, fmaf(xA.y, g1.y, g1.z)), 0.0f);
                float s10 = fmaxf(fmaf(xB.x, g0.x, fmaf(xB.y, g0.y, g0.z)), 0.0f);
                float s11 = fmaxf(fmaf(xB.x, g1.x, fmaf(xB.y, g1.y, g1.z)), 0.0f);
                float s08 = fmaxf(fmaf(xA.x, g8.x, fmaf(xA.y, g8.y, g8.z)), 0.0f);
                float s09 = fmaxf(fmaf(xA.x, g9.x, fmaf(xA.y, g9.y, g9.z)), 0.0f);
                float s18 = fmaxf(fmaf(xB.x, g8.x, fmaf(xB.y, g8.y, g8.z)), 0.0f);
                float s19 = fmaxf(fmaf(xB.x, g9.x, fmaf(xB.y, g9.y, g9.z)), 0.0f);
                float h00 = fhi(s00), h01 = fhi(s01), h10 = fhi(s10), h11 = fhi(s11);
                float h08 = fhi(s08), h09 = fhi(s09), h18 = fhi(s18), h19 = fhi(s19);
                int o = st * 4;
                sfH[kt][o + 0] = pk(h00, h01); sfH[kt][o + 1] = pk(h10, h11);
                sfH[kt][o + 2] = pk(h08, h09); sfH[kt][o + 3] = pk(h18, h19);
                sfL[kt][o + 0] = pk(s00 - h00, s01 - h01);
                sfL[kt][o + 1] = pk(s10 - h10, s11 - h11);
                sfL[kt][o + 2] = pk(s08 - h08, s09 - h09);
                sfL[kt][o + 3] = pk(s18 - h18, s19 - h19);
            }
        }

        // ---- per-nt: accumulate gate tiles for BOTH sets, update h ----
        uint32_t nhh[4][8], nhl[4][8];
#pragma unroll
        for (int nt = 0; nt < 8; nt++) {
            float aR[8] = {0,0,0,0,0,0,0,0}, aZ[8] = {0,0,0,0,0,0,0,0};
            float aI[8] = {0,0,0,0,0,0,0,0}, aN[8] = {0,0,0,0,0,0,0,0};
#pragma unroll
            for (int kt = 0; kt < 8; kt++) {
                const uint32_t* xH = (kt < 4) ? sfH[kt] : hh[kt - 4];
                const uint32_t* xL = (kt < 4) ? sfL[kt] : hl[kt - 4];
                uint4 bR = *(const uint4*)(smem + SM_B1 +
                             (uint32_t)((kt * 16 + nt) * 32 + lane) * 16);
                mma16816(aR,     xH,     bR.x, bR.y);
                mma16816(aR + 4, xH + 4, bR.x, bR.y);
                mma16816(aR,     xH,     bR.z, bR.w);
                mma16816(aR + 4, xH + 4, bR.z, bR.w);
                mma16816(aR,     xL,     bR.x, bR.y);
                mma16816(aR + 4, xL + 4, bR.x, bR.y);
                uint4 bZ = *(const uint4*)(smem + SM_B1 +
                             (uint32_t)((kt * 16 + nt + 8) * 32 + lane) * 16);
                mma16816(aZ,     xH,     bZ.x, bZ.y);
                mma16816(aZ + 4, xH + 4, bZ.x, bZ.y);
                mma16816(aZ,     xH,     bZ.z, bZ.w);
                mma16816(aZ + 4, xH + 4, bZ.z, bZ.w);
                mma16816(aZ,     xL,     bZ.x, bZ.y);
                mma16816(aZ + 4, xL + 4, bZ.x, bZ.y);
                if (kt < 4) {
                    uint4 b2 = *(const uint4*)(smem + SM_B2 +
                                 (uint32_t)((kt * 8 + nt) * 32 + lane) * 16);
                    mma16816(aI,     sfH[kt],     b2.x, b2.y);
                    mma16816(aI + 4, sfH[kt] + 4, b2.x, b2.y);
                    mma16816(aI,     sfH[kt],     b2.z, b2.w);
                    mma16816(aI + 4, sfH[kt] + 4, b2.z, b2.w);
                    mma16816(aI,     sfL[kt],     b2.x, b2.y);
                    mma16816(aI + 4, sfL[kt] + 4, b2.x, b2.y);
                    uint4 b3 = *(const uint4*)(smem + SM_B3 +
                                 (uint32_t)((kt * 8 + nt) * 32 + lane) * 16);
                    mma16816(aN,     hh[kt],     b3.x, b3.y);
                    mma16816(aN + 4, hh[kt] + 4, b3.x, b3.y);
                    mma16816(aN,     hh[kt],     b3.z, b3.w);
                    mma16816(aN + 4, hh[kt] + 4, b3.z, b3.w);
                    mma16816(aN,     hl[kt],     b3.x, b3.y);
                    mma16816(aN + 4, hl[kt] + 4, b3.x, b3.y);
                }
            }
            int kt2 = nt >> 1, base = (nt & 1) * 2;
            int j0 = 8 * nt + 2 * tig;
            float4 bj0 = sBIAS[j0];
            float4 bj1 = sBIAS[j0 + 1];
#pragma unroll
            for (int st = 0; st < 2; st++) {
                int o = st * 4;
                float2 oh0H = upk(hh[kt2][o + base]),     oh0L = upk(hl[kt2][o + base]);
                float2 oh1H = upk(hh[kt2][o + base + 1]), oh1L = upk(hl[kt2][o + base + 1]);
                float hold[4] = { oh0H.x + oh0L.x, oh0H.y + oh0L.y,
                                  oh1H.x + oh1L.x, oh1H.y + oh1L.y };
                float hn[4];
#pragma unroll
                for (int q = 0; q < 4; q++) {
                    float4 bb = (q & 1) ? bj1 : bj0;
                    float r  = fsigmoid(aR[o + q] + bb.x);
                    float z  = fsigmoid(aZ[o + q] + bb.y);
                    float nn = ftanh(fmaf(r, aN[o + q] + bb.w, aI[o + q] + bb.z));
                    hn[q] = fmaf(z, hold[q] - nn, nn);
                }
                float p0 = fhi(hn[0]), p1 = fhi(hn[1]);
                float p2 = fhi(hn[2]), p3 = fhi(hn[3]);
                nhh[kt2][o + base]     = pk(p0, p1);
                nhh[kt2][o + base + 1] = pk(p2, p3);
                nhl[kt2][o + base]     = pk(hn[0] - p0, hn[1] - p1);
                nhl[kt2][o + base + 1] = pk(hn[2] - p2, hn[3] - p3);
            }
        }
#pragma unroll
        for (int kt = 0; kt < 4; kt++)
#pragma unroll
            for (int q = 0; q < 8; q++) { hh[kt][q] = nhh[kt][q]; hl[kt][q] = nhl[kt][q]; }
    }

    // ---- FC readout: 4 node rows per thread ----
    float pA = 0.0f, pB = 0.0f, pC = 0.0f, pD = 0.0f;
#pragma unroll
    for (int nt = 0; nt < 8; nt++) {
        int kt2 = nt >> 1, base = (nt & 1) * 2;
        int j0 = 8 * nt + 2 * tig;
        float w0 = sWFC[j0], w1 = sWFC[j0 + 1];
        float2 aHv = upk(hh[kt2][base]),     aLv = upk(hl[kt2][base]);
        float2 bHv = upk(hh[kt2][base + 1]), bLv = upk(hl[kt2][base + 1]);
        pA = fmaf(aHv.x + aLv.x, w0, fmaf(aHv.y + aLv.y, w1, pA));
        pB = fmaf(bHv.x + bLv.x, w0, fmaf(bHv.y + bLv.y, w1, pB));
        float2 cHv = upk(hh[kt2][4 + base]),     cLv = upk(hl[kt2][4 + base]);
        float2 dHv = upk(hh[kt2][4 + base + 1]), dLv = upk(hl[kt2][4 + base + 1]);
        pC = fmaf(cHv.x + cLv.x, w0, fmaf(cHv.y + cLv.y, w1, pC));
        pD = fmaf(dHv.x + dLv.x, w0, fmaf(dHv.y + dLv.y, w1, pD));
    }
    pA += __shfl_xor_sync(0xFFFFFFFF, pA, 1);
    pA += __shfl_xor_sync(0xFFFFFFFF, pA, 2);
    pB += __shfl_xor_sync(0xFFFFFFFF, pB, 1);
    pB += __shfl_xor_sync(0xFFFFFFFF, pB, 2);
    pC += __shfl_xor_sync(0xFFFFFFFF, pC, 1);
    pC += __shfl_xor_sync(0xFFFFFFFF, pC, 2);
    pD += __shfl_xor_sync(0xFFFFFFFF, pD, 1);
    pD += __shfl_xor_sync(0xFFFFFFFF, pD, 2);
    if (tig == 0) {
        float bfc = b_fc[0];
        int nA = node0 + n0, nB = nA + 8, nC = nA + 16, nD = nA + 24;
        if (nA < NN) out[nA] = pA + bfc;
        if (nB < NN) out[nB] = pB + bfc;
        if (nC < NN) out[nC] = pC + bfc;
        if (nD < NN) out[nD] = pD + bfc;
    }
}

// ---------------- launch ----------------
extern "C" void kernel_launch(void* const* d_in, const int* in_sizes, int n_in,
                              void* d_out, int out_size) {
    const float* x     = (const float*)d_in[0];
    const int*   ei32  = (const int*)d_in[1];
    const float* W_gcn = (const float*)d_in[2];
    const float* b_gcn = (const float*)d_in[3];
    const float* W_ih  = (const float*)d_in[4];
    const float* W_hh  = (const float*)d_in[5];
    const float* b_ih  = (const float*)d_in[6];
    const float* b_hh  = (const float*)d_in[7];
    const float* W_fc  = (const float*)d_in[8];
    const float* b_fc  = (const float*)d_in[9];
    float* out = (float*)d_out;

    static bool attr_set = false;
    if (!attr_set) {
        cudaFuncSetAttribute(k_fused, cudaFuncAttributeMaxDynamicSharedMemorySize,
                             SM_TOTAL);
        attr_set = true;
    }

    k_initprobe<<<SCAN_BLOCKS, 256>>>(ei32);
    k_count<<<(NE + 255) / 256, 256>>>(ei32);
    k_scan1<<<SCAN_BLOCKS, 256>>>();
    k_scan2<<<1, 256>>>();
    k_scan3<<<SCAN_BLOCKS, 256>>>();
    k_fill<<<(NE + 255) / 256, 256>>>(ei32);
    k_gather<<<(NN * 32 + 255) / 256, 256>>>(x);
    k_fused<<<(NN + NPB - 1) / NPB, THREADS, SM_TOTAL>>>(
        x, W_gcn, b_gcn, W_ih, W_hh, b_ih, b_hh, W_fc, b_fc, out);
}

// round 13
// speedup vs baseline: 1.1794x; 1.1794x over previous
#include <cuda_runtime.h>
#include <cuda_bf16.h>
#include <cstdint>
#include <math.h>

#define NN 50000
#define NE 800000
#define TT 12
#define NPB 128
#define SCAN_BLOCKS 196   // ceil(50000/256)

// ---------------- device scratch (no allocations) ----------------
__device__ int   g_cnt[NN];
__device__ int   g_off[NN];
__device__ int   g_fill[NN];
__device__ int   g_srcs[NE];
__device__ float g_dinv[NN];
__device__ float g_agg[NN * 24];    // raw: sum_e dinv[src]*x[src][c]
__device__ int   g_bsum[256];
__device__ int   g_bpre[256];
__device__ int   g_is64;

// ---------------- preprocessing: CSR build + gather ----------------
__global__ void k_initprobe(const int* __restrict__ ei32) {
    int i = blockIdx.x * blockDim.x + threadIdx.x;
    int stride = gridDim.x * blockDim.x;
    for (int j = i; j < NN; j += stride) g_cnt[j] = 0;
    if (blockIdx.x == 0) {
        int nz = 0;
        for (int j = threadIdx.x; j < 1024; j += blockDim.x)
            if (ei32[2 * j + 1] != 0) nz = 1;
        int any = __syncthreads_or(nz);
        if (threadIdx.x == 0) g_is64 = any ? 0 : 1;
    }
}

__device__ __forceinline__ void load_edge(const int* ei32, int e, int& s, int& d) {
    if (g_is64) { s = ei32[2 * e]; d = ei32[2 * (NE + e)]; }
    else        { s = ei32[e];     d = ei32[NE + e]; }
}

__global__ void k_count(const int* __restrict__ ei32) {
    int e = blockIdx.x * blockDim.x + threadIdx.x;
    if (e >= NE) return;
    int s, d;
    load_edge(ei32, e, s, d);
    atomicAdd(&g_cnt[d], 1);
}

__global__ void k_scan1() {
    __shared__ int sc[256];
    int tid = threadIdx.x;
    int i = blockIdx.x * 256 + tid;
    int v = (i < NN) ? g_cnt[i] : 0;
    sc[tid] = v;
    __syncthreads();
#pragma unroll
    for (int ofs = 1; ofs < 256; ofs <<= 1) {
        int t = (tid >= ofs) ? sc[tid - ofs] : 0;
        __syncthreads();
        sc[tid] += t;
        __syncthreads();
    }
    if (i < NN) g_off[i] = sc[tid] - v;
    if (tid == 255) g_bsum[blockIdx.x] = sc[255];
}

__global__ void k_scan2() {
    __shared__ int sc[256];
    int tid = threadIdx.x;
    int v = (tid < SCAN_BLOCKS) ? g_bsum[tid] : 0;
    sc[tid] = v;
    __syncthreads();
#pragma unroll
    for (int ofs = 1; ofs < 256; ofs <<= 1) {
        int t = (tid >= ofs) ? sc[tid - ofs] : 0;
        __syncthreads();
        sc[tid] += t;
        __syncthreads();
    }
    g_bpre[tid] = sc[tid] - v;
}

__global__ void k_scan3() {
    int i = blockIdx.x * 256 + threadIdx.x;
    if (i >= NN) return;
    int off = g_off[i] + g_bpre[blockIdx.x];
    g_off[i]  = off;
    g_fill[i] = off;
    g_dinv[i] = rsqrtf((float)g_cnt[i] + 1.0f);
}

__global__ void k_fill(const int* __restrict__ ei32) {
    int e = blockIdx.x * blockDim.x + threadIdx.x;
    if (e >= NE) return;
    int s, d;
    load_edge(ei32, e, s, d);
    int pos = atomicAdd(&g_fill[d], 1);
    g_srcs[pos] = s;
}

__global__ void k_gather(const float* __restrict__ x) {
    int w = (blockIdx.x * blockDim.x + threadIdx.x) >> 5;
    int lane = threadIdx.x & 31;
    if (w >= NN || lane >= 24) return;
    int start = g_off[w];
    int end = (w + 1 < NN) ? g_off[w + 1] : NE;
    float acc = 0.0f;
    for (int e = start; e < end; e++) {
        int s = g_srcs[e];
        acc = fmaf(g_dinv[s], __ldg(x + (size_t)s * 24 + lane), acc);
    }
    g_agg[(size_t)w * 24 + lane] = acc;
}

// ---------------- fast math (MUFU-based) ----------------
__device__ __forceinline__ float fsigmoid(float x) {
    float e, r;
    asm("ex2.approx.ftz.f32 %0, %1;" : "=f"(e) : "f"(-x * 1.4426950408889634f));
    asm("rcp.approx.ftz.f32 %0, %1;" : "=f"(r) : "f"(1.0f + e));
    return r;
}
__device__ __forceinline__ float ftanh(float x) {
    float r;
    asm("tanh.approx.f32 %0, %1;" : "=f"(r) : "f"(x));
    return r;
}

// ---------------- bf16 / tf32 helpers ----------------
__device__ __forceinline__ float fhi(float x) {
    return __bfloat162float(__float2bfloat16_rn(x));
}
__device__ __forceinline__ uint32_t pk(float a, float b) {
    __nv_bfloat162 t = __floats2bfloat162_rn(a, b);
    return *reinterpret_cast<uint32_t*>(&t);
}
__device__ __forceinline__ float2 upk(uint32_t u) {
    __nv_bfloat162 t = *reinterpret_cast<__nv_bfloat162*>(&u);
    return make_float2(__low2float(t), __high2float(t));
}
__device__ __forceinline__ uint32_t tf32c(float x) {
    uint32_t r;
    asm("cvt.rna.tf32.f32 %0, %1;" : "=r"(r) : "f"(x));
    return r;
}

// m16n8k16 row.col bf16 MMA, fp32 accumulate
__device__ __forceinline__ void mma16816(float* d, const uint32_t* a,
                                         uint32_t b0, uint32_t b1) {
    asm volatile(
        "mma.sync.aligned.m16n8k16.row.col.f32.bf16.bf16.f32 "
        "{%0,%1,%2,%3}, {%4,%5,%6,%7}, {%8,%9}, {%0,%1,%2,%3};"
        : "+f"(d[0]), "+f"(d[1]), "+f"(d[2]), "+f"(d[3])
        : "r"(a[0]), "r"(a[1]), "r"(a[2]), "r"(a[3]), "r"(b0), "r"(b1));
}
// m16n8k8 row.col tf32 MMA, fp32 accumulate
__device__ __forceinline__ void mma1688t(float* d, const uint32_t* a,
                                         uint32_t b0, uint32_t b1) {
    asm volatile(
        "mma.sync.aligned.m16n8k8.row.col.f32.tf32.tf32.f32 "
        "{%0,%1,%2,%3}, {%4,%5,%6,%7}, {%8,%9}, {%0,%1,%2,%3};"
        : "+f"(d[0]), "+f"(d[1]), "+f"(d[2]), "+f"(d[3])
        : "r"(a[0]), "r"(a[1]), "r"(a[2]), "r"(a[3]), "r"(b0), "r"(b1));
}

// ---------------- smem layout (bytes) ----------------
#define SM_B1    0          // 128 frags x 32 lanes x 16B = 64KB (rz: K=128,N=128)
#define SM_B2    65536      // 16KB (Wih_n: K=64,N=64) — tf32 frags
#define SM_B3    81920      // 16KB (Whh_n) — bf16 hi/lo frags
#define SM_XA    98304      // float2[12][128] = 12KB
#define SM_WG3   110592     // float4[64] : {wg0, wg1, bg, 0}
#define SM_BIAS  111616     // float4[64] : {br, bz, bin, bhn}
#define SM_WFC   112640     // float[64]
#define SM_TOTAL 112896     // 2 CTAs per SM

__global__ void __launch_bounds__(256, 2)
k_fused(const float* __restrict__ x,
        const float* __restrict__ W_gcn, const float* __restrict__ b_gcn,
        const float* __restrict__ W_ih,  const float* __restrict__ W_hh,
        const float* __restrict__ b_ih,  const float* __restrict__ b_hh,
        const float* __restrict__ W_fc,  const float* __restrict__ b_fc,
        float* __restrict__ out) {
    extern __shared__ char smem[];
    const int tid  = threadIdx.x;
    const int wid  = tid >> 5;
    const int lane = tid & 31;
    const int gid  = lane >> 2;
    const int tig  = lane & 3;
    const int node0 = blockIdx.x * NPB;
    const int n0 = wid * 16 + gid;
    const int n1 = n0 + 8;

    // ---- build B fragments ----
    // B1 kt<4 (S-side of r,z): tf32 layout {k=tig, tig+4, tig+8, tig+12}
    // B1 kt>=4 (H-side): bf16 hi/lo.  B2: tf32.  B3: bf16 hi/lo.
    for (int i = tid; i < 6144; i += 256) {
        uint4 v;
        uint32_t dst;
        if (i < 4096) {                       // B1: rz, 8kt x 16nt
            int f = i >> 5, l = i & 31;
            int kt = f >> 4, nt = f & 15;
            int g = l >> 2, tg = l & 3;
            int j = 8 * nt + g;
            if (kt < 4) {                     // tf32: W_ih[j][16kt + tg + {0,4,8,12}]
                const float* Wr = W_ih + j * 64 + 16 * kt + tg;
                v.x = tf32c(Wr[0]);
                v.y = tf32c(Wr[4]);
                v.z = tf32c(Wr[8]);
                v.w = tf32c(Wr[12]);
            } else {                          // bf16 hi/lo: W_hh
                const float* Wr = W_hh + j * 64 + 16 * (kt - 4) + 2 * tg;
                float w0 = Wr[0], w1 = Wr[1], w8 = Wr[8], w9 = Wr[9];
                float h0 = fhi(w0), h1 = fhi(w1), h8 = fhi(w8), h9 = fhi(w9);
                v.x = pk(h0, h1);
                v.y = pk(h8, h9);
                v.z = pk(w0 - h0, w1 - h1);
                v.w = pk(w8 - h8, w9 - h9);
            }
            dst = SM_B1 + (uint32_t)(f * 32 + l) * 16;
        } else if (i < 5120) {                // B2: Wih_n, tf32
            int ii = i - 4096;
            int f = ii >> 5, l = ii & 31;
            int kt = f >> 3, nt = f & 7;
            int g = l >> 2, tg = l & 3;
            int j = 8 * nt + g;
            const float* Wr = W_ih + (128 + j) * 64 + 16 * kt + tg;
            v.x = tf32c(Wr[0]);
            v.y = tf32c(Wr[4]);
            v.z = tf32c(Wr[8]);
            v.w = tf32c(Wr[12]);
            dst = SM_B2 + (uint32_t)(f * 32 + l) * 16;
        } else {                              // B3: Whh_n, bf16 hi/lo
            int ii = i - 5120;
            int f = ii >> 5, l = ii & 31;
            int kt = f >> 3, nt = f & 7;
            int g = l >> 2, tg = l & 3;
            int j = 8 * nt + g;
            const float* Wr = W_hh + (128 + j) * 64 + 16 * kt + 2 * tg;
            float w0 = Wr[0], w1 = Wr[1], w8 = Wr[8], w9 = Wr[9];
            float h0 = fhi(w0), h1 = fhi(w1), h8 = fhi(w8), h9 = fhi(w9);
            v.x = pk(h0, h1);
            v.y = pk(h8, h9);
            v.z = pk(w0 - h0, w1 - h1);
            v.w = pk(w8 - h8, w9 - h9);
            dst = SM_B3 + (uint32_t)(f * 32 + l) * 16;
        }
        *(uint4*)(smem + dst) = v;
    }

    // ---- XA: dinv*(agg_raw + dinv*x), layout float2[t][n] ----
    float* sXA = (float*)(smem + SM_XA);
    for (int i = tid; i < NPB * 24; i += 256) {
        int n = i / 24, cc = i - n * 24;
        int t = cc >> 1, c = cc & 1;
        int node = node0 + n;
        float v = 0.0f;
        if (node < NN) {
            float dv = g_dinv[node];
            v = dv * (g_agg[(size_t)node * 24 + cc] + dv * x[(size_t)node * 24 + cc]);
        }
        sXA[(t * 128 + n) * 2 + c] = v;
    }
    if (tid < 64) {
        float4* wg3 = (float4*)(smem + SM_WG3);
        wg3[tid] = make_float4(W_gcn[tid], W_gcn[64 + tid], b_gcn[tid], 0.0f);
        float4* bia = (float4*)(smem + SM_BIAS);
        bia[tid] = make_float4(b_ih[tid] + b_hh[tid],
                               b_ih[64 + tid] + b_hh[64 + tid],
                               b_ih[128 + tid], b_hh[128 + tid]);
        ((float*)(smem + SM_WFC))[tid] = W_fc[tid];
    }
    __syncthreads();

    const float4* sWG3  = (const float4*)(smem + SM_WG3);
    const float4* sBIAS = (const float4*)(smem + SM_BIAS);
    const float*  sWFC  = (const float*)(smem + SM_WFC);

    // ---- hidden state packed bf16 hi/lo A-fragments (m16n8k16) ----
    uint32_t hh[4][4], hl[4][4];
#pragma unroll
    for (int kt = 0; kt < 4; kt++)
#pragma unroll
        for (int q = 0; q < 4; q++) { hh[kt][q] = 0u; hl[kt][q] = 0u; }

#pragma unroll 1
    for (int t = 0; t < TT; t++) {
        float2 xaA = *(const float2*)(sXA + (t * 128 + n0) * 2);
        float2 xaB = *(const float2*)(sXA + (t * 128 + n1) * 2);

        // ---- S fragments in tf32 m16n8k8 layout ----
        // sf[kt][0..3] = k-half0 {cols 16kt+tig, +4}; sf[kt][4..7] = k-half1 {+8, +12}
        uint32_t sf[4][8];
#pragma unroll
        for (int kt = 0; kt < 4; kt++) {
            int kb = 16 * kt + tig;
            float4 w0  = sWG3[kb];
            float4 w4  = sWG3[kb + 4];
            float4 w8  = sWG3[kb + 8];
            float4 w12 = sWG3[kb + 12];
            sf[kt][0] = tf32c(fmaxf(fmaf(xaA.x, w0.x,  fmaf(xaA.y, w0.y,  w0.z)),  0.0f));
            sf[kt][1] = tf32c(fmaxf(fmaf(xaB.x, w0.x,  fmaf(xaB.y, w0.y,  w0.z)),  0.0f));
            sf[kt][2] = tf32c(fmaxf(fmaf(xaA.x, w4.x,  fmaf(xaA.y, w4.y,  w4.z)),  0.0f));
            sf[kt][3] = tf32c(fmaxf(fmaf(xaB.x, w4.x,  fmaf(xaB.y, w4.y,  w4.z)),  0.0f));
            sf[kt][4] = tf32c(fmaxf(fmaf(xaA.x, w8.x,  fmaf(xaA.y, w8.y,  w8.z)),  0.0f));
            sf[kt][5] = tf32c(fmaxf(fmaf(xaB.x, w8.x,  fmaf(xaB.y, w8.y,  w8.z)),  0.0f));
            sf[kt][6] = tf32c(fmaxf(fmaf(xaA.x, w12.x, fmaf(xaA.y, w12.y, w12.z)), 0.0f));
            sf[kt][7] = tf32c(fmaxf(fmaf(xaB.x, w12.x, fmaf(xaB.y, w12.y, w12.z)), 0.0f));
        }

        // ---- per-nt: accumulate gate tiles, update h, repack ----
        uint32_t nhh[4][4], nhl[4][4];
#pragma unroll
        for (int nt = 0; nt < 8; nt++) {
            float aR[4] = {0, 0, 0, 0}, aZ[4] = {0, 0, 0, 0};
            float aI[4] = {0, 0, 0, 0}, aN[4] = {0, 0, 0, 0};
            // S-side (tf32, kt<4) + h_n (bf16)
#pragma unroll
            for (int kt = 0; kt < 4; kt++) {
                uint4 bR = *(const uint4*)(smem + SM_B1 +
                             (uint32_t)((kt * 16 + nt) * 32 + lane) * 16);
                mma1688t(aR, &sf[kt][0], bR.x, bR.y);
                mma1688t(aR, &sf[kt][4], bR.z, bR.w);
                uint4 bZ = *(const uint4*)(smem + SM_B1 +
                             (uint32_t)((kt * 16 + nt + 8) * 32 + lane) * 16);
                mma1688t(aZ, &sf[kt][0], bZ.x, bZ.y);
                mma1688t(aZ, &sf[kt][4], bZ.z, bZ.w);
                uint4 b2 = *(const uint4*)(smem + SM_B2 +
                             (uint32_t)((kt * 8 + nt) * 32 + lane) * 16);
                mma1688t(aI, &sf[kt][0], b2.x, b2.y);
                mma1688t(aI, &sf[kt][4], b2.z, b2.w);
                uint4 b3 = *(const uint4*)(smem + SM_B3 +
                             (uint32_t)((kt * 8 + nt) * 32 + lane) * 16);
                mma16816(aN, hh[kt], b3.x, b3.y);
                mma16816(aN, hh[kt], b3.z, b3.w);
                mma16816(aN, hl[kt], b3.x, b3.y);
            }
            // H-side of r,z (bf16, kt 4..7)
#pragma unroll
            for (int kt = 0; kt < 4; kt++) {
                uint4 cR = *(const uint4*)(smem + SM_B1 +
                             (uint32_t)(((kt + 4) * 16 + nt) * 32 + lane) * 16);
                mma16816(aR, hh[kt], cR.x, cR.y);
                mma16816(aR, hh[kt], cR.z, cR.w);
                mma16816(aR, hl[kt], cR.x, cR.y);
                uint4 cZ = *(const uint4*)(smem + SM_B1 +
                             (uint32_t)(((kt + 4) * 16 + nt + 8) * 32 + lane) * 16);
                mma16816(aZ, hh[kt], cZ.x, cZ.y);
                mma16816(aZ, hh[kt], cZ.z, cZ.w);
                mma16816(aZ, hl[kt], cZ.x, cZ.y);
            }
            int kt2 = nt >> 1, base = (nt & 1) * 2;
            float2 oh0H = upk(hh[kt2][base]),     oh0L = upk(hl[kt2][base]);
            float2 oh1H = upk(hh[kt2][base + 1]), oh1L = upk(hl[kt2][base + 1]);
            float hold[4] = { oh0H.x + oh0L.x, oh0H.y + oh0L.y,
                              oh1H.x + oh1L.x, oh1H.y + oh1L.y };
            int j0 = 8 * nt + 2 * tig;
            float4 bj0 = sBIAS[j0];
            float4 bj1 = sBIAS[j0 + 1];
            float hn[4];
#pragma unroll
            for (int q = 0; q < 4; q++) {
                float4 bb = (q & 1) ? bj1 : bj0;
                float r  = fsigmoid(aR[q] + bb.x);
                float z  = fsigmoid(aZ[q] + bb.y);
                float nn = ftanh(fmaf(r, aN[q] + bb.w, aI[q] + bb.z));
                hn[q] = fmaf(z, hold[q] - nn, nn);
            }
            float p0 = fhi(hn[0]), p1 = fhi(hn[1]);
            float p2 = fhi(hn[2]), p3 = fhi(hn[3]);
            nhh[kt2][base]     = pk(p0, p1);
            nhh[kt2][base + 1] = pk(p2, p3);
            nhl[kt2][base]     = pk(hn[0] - p0, hn[1] - p1);
            nhl[kt2][base + 1] = pk(hn[2] - p2, hn[3] - p3);
        }
#pragma unroll
        for (int kt = 0; kt < 4; kt++)
#pragma unroll
            for (int q = 0; q < 4; q++) { hh[kt][q] = nhh[kt][q]; hl[kt][q] = nhl[kt][q]; }
    }

    // ---- FC readout ----
    float pA = 0.0f, pB = 0.0f;
#pragma unroll
    for (int nt = 0; nt < 8; nt++) {
        int kt2 = nt >> 1, base = (nt & 1) * 2;
        float2 aHv = upk(hh[kt2][base]),     aLv = upk(hl[kt2][base]);
        float2 bHv = upk(hh[kt2][base + 1]), bLv = upk(hl[kt2][base + 1]);
        int j0 = 8 * nt + 2 * tig;
        float w0 = sWFC[j0], w1 = sWFC[j0 + 1];
        pA = fmaf(aHv.x + aLv.x, w0, fmaf(aHv.y + aLv.y, w1, pA));
        pB = fmaf(bHv.x + bLv.x, w0, fmaf(bHv.y + bLv.y, w1, pB));
    }
    pA += __shfl_xor_sync(0xFFFFFFFF, pA, 1);
    pA += __shfl_xor_sync(0xFFFFFFFF, pA, 2);
    pB += __shfl_xor_sync(0xFFFFFFFF, pB, 1);
    pB += __shfl_xor_sync(0xFFFFFFFF, pB, 2);
    if (tig == 0) {
        float bfc = b_fc[0];
        int nodeA = node0 + n0;
        int nodeB = node0 + n1;
        if (nodeA < NN) out[nodeA] = pA + bfc;
        if (nodeB < NN) out[nodeB] = pB + bfc;
    }
}

// ---------------- launch ----------------
extern "C" void kernel_launch(void* const* d_in, const int* in_sizes, int n_in,
                              void* d_out, int out_size) {
    const float* x     = (const float*)d_in[0];
    const int*   ei32  = (const int*)d_in[1];
    const float* W_gcn = (const float*)d_in[2];
    const float* b_gcn = (const float*)d_in[3];
    const float* W_ih  = (const float*)d_in[4];
    const float* W_hh  = (const float*)d_in[5];
    const float* b_ih  = (const float*)d_in[6];
    const float* b_hh  = (const float*)d_in[7];
    const float* W_fc  = (const float*)d_in[8];
    const float* b_fc  = (const float*)d_in[9];
    float* out = (float*)d_out;

    static bool attr_set = false;
    if (!attr_set) {
        cudaFuncSetAttribute(k_fused, cudaFuncAttributeMaxDynamicSharedMemorySize,
                             SM_TOTAL);
        attr_set = true;
    }

    k_initprobe<<<SCAN_BLOCKS, 256>>>(ei32);
    k_count<<<(NE + 255) / 256, 256>>>(ei32);
    k_scan1<<<SCAN_BLOCKS, 256>>>();
    k_scan2<<<1, 256>>>();
    k_scan3<<<SCAN_BLOCKS, 256>>>();
    k_fill<<<(NE + 255) / 256, 256>>>(ei32);
    k_gather<<<(NN * 32 + 255) / 256, 256>>>(x);
    k_fused<<<(NN + NPB - 1) / NPB, 256, SM_TOTAL>>>(
        x, W_gcn, b_gcn, W_ih, W_hh, b_ih, b_hh, W_fc, b_fc, out);
}

// round 14
// speedup vs baseline: 1.3774x; 1.1678x over previous
#include <cuda_runtime.h>
#include <cuda_bf16.h>
#include <cstdint>
#include <math.h>

#define NN 50000
#define NE 800000
#define TT 12
#define NPB 128
#define SCAN_BLOCKS 196   // ceil(50000/256)

// ---------------- device scratch (no allocations) ----------------
__device__ int   g_cnt[NN];
__device__ int   g_off[NN];
__device__ int   g_fill[NN];
__device__ int   g_srcs[NE];
__device__ float g_dinv[NN];
__device__ float g_agg[NN * 24];    // raw: sum_e dinv[src]*x[src][c]
__device__ int   g_bsum[256];
__device__ int   g_bpre[256];
__device__ int   g_is64;

// ---------------- preprocessing: CSR build + gather ----------------
__global__ void k_initprobe(const int* __restrict__ ei32) {
    int i = blockIdx.x * blockDim.x + threadIdx.x;
    int stride = gridDim.x * blockDim.x;
    for (int j = i; j < NN; j += stride) g_cnt[j] = 0;
    if (blockIdx.x == 0) {
        int nz = 0;
        for (int j = threadIdx.x; j < 1024; j += blockDim.x)
            if (ei32[2 * j + 1] != 0) nz = 1;
        int any = __syncthreads_or(nz);
        if (threadIdx.x == 0) g_is64 = any ? 0 : 1;
    }
}

__device__ __forceinline__ void load_edge(const int* ei32, int e, int& s, int& d) {
    if (g_is64) { s = ei32[2 * e]; d = ei32[2 * (NE + e)]; }
    else        { s = ei32[e];     d = ei32[NE + e]; }
}

__global__ void k_count(const int* __restrict__ ei32) {
    int e = blockIdx.x * blockDim.x + threadIdx.x;
    if (e >= NE) return;
    int s, d;
    load_edge(ei32, e, s, d);
    atomicAdd(&g_cnt[d], 1);
}

__global__ void k_scan1() {
    __shared__ int sc[256];
    int tid = threadIdx.x;
    int i = blockIdx.x * 256 + tid;
    int v = (i < NN) ? g_cnt[i] : 0;
    sc[tid] = v;
    __syncthreads();
#pragma unroll
    for (int ofs = 1; ofs < 256; ofs <<= 1) {
        int t = (tid >= ofs) ? sc[tid - ofs] : 0;
        __syncthreads();
        sc[tid] += t;
        __syncthreads();
    }
    if (i < NN) g_off[i] = sc[tid] - v;
    if (tid == 255) g_bsum[blockIdx.x] = sc[255];
}

__global__ void k_scan2() {
    __shared__ int sc[256];
    int tid = threadIdx.x;
    int v = (tid < SCAN_BLOCKS) ? g_bsum[tid] : 0;
    sc[tid] = v;
    __syncthreads();
#pragma unroll
    for (int ofs = 1; ofs < 256; ofs <<= 1) {
        int t = (tid >= ofs) ? sc[tid - ofs] : 0;
        __syncthreads();
        sc[tid] += t;
        __syncthreads();
    }
    g_bpre[tid] = sc[tid] - v;
}

__global__ void k_scan3() {
    int i = blockIdx.x * 256 + threadIdx.x;
    if (i >= NN) return;
    int off = g_off[i] + g_bpre[blockIdx.x];
    g_off[i]  = off;
    g_fill[i] = off;
    g_dinv[i] = rsqrtf((float)g_cnt[i] + 1.0f);
}

__global__ void k_fill(const int* __restrict__ ei32) {
    int e = blockIdx.x * blockDim.x + threadIdx.x;
    if (e >= NE) return;
    int s, d;
    load_edge(ei32, e, s, d);
    int pos = atomicAdd(&g_fill[d], 1);
    g_srcs[pos] = s;
}

__global__ void k_gather(const float* __restrict__ x) {
    int w = (blockIdx.x * blockDim.x + threadIdx.x) >> 5;
    int lane = threadIdx.x & 31;
    if (w >= NN || lane >= 24) return;
    int start = g_off[w];
    int end = (w + 1 < NN) ? g_off[w + 1] : NE;
    float acc = 0.0f;
    for (int e = start; e < end; e++) {
        int s = g_srcs[e];
        acc = fmaf(g_dinv[s], __ldg(x + (size_t)s * 24 + lane), acc);
    }
    g_agg[(size_t)w * 24 + lane] = acc;
}

// ---------------- fast math (MUFU-based) ----------------
__device__ __forceinline__ float fsigmoid(float x) {
    float e, r;
    asm("ex2.approx.ftz.f32 %0, %1;" : "=f"(e) : "f"(-x * 1.4426950408889634f));
    asm("rcp.approx.ftz.f32 %0, %1;" : "=f"(r) : "f"(1.0f + e));
    return r;
}
__device__ __forceinline__ float ftanh(float x) {
    float r;
    asm("tanh.approx.f32 %0, %1;" : "=f"(r) : "f"(x));
    return r;
}

// ---------------- tf32 helpers ----------------
__device__ __forceinline__ uint32_t tf32c(float x) {
    uint32_t r;
    asm("cvt.rna.tf32.f32 %0, %1;" : "=r"(r) : "f"(x));
    return r;
}

// m16n8k8 row.col tf32 MMA, fp32 accumulate; A fed as raw fp32 (HW truncates)
__device__ __forceinline__ void mma1688f(float* d, const float* a,
                                         uint32_t b0, uint32_t b1) {
    asm volatile(
        "mma.sync.aligned.m16n8k8.row.col.f32.tf32.tf32.f32 "
        "{%0,%1,%2,%3}, {%4,%5,%6,%7}, {%8,%9}, {%0,%1,%2,%3};"
        : "+f"(d[0]), "+f"(d[1]), "+f"(d[2]), "+f"(d[3])
        : "r"(__float_as_uint(a[0])), "r"(__float_as_uint(a[1])),
          "r"(__float_as_uint(a[2])), "r"(__float_as_uint(a[3])),
          "r"(b0), "r"(b1));
}

// column permutation: B fragment n-slot g holds weight row j = 8*nt + perm(g)
// so D slots {2tig, 2tig+1} = j {tig, tig+4} == tf32 A-fragment column layout
__device__ __forceinline__ int permj(int g) { return (g >> 1) + 4 * (g & 1); }

// ---------------- smem layout (bytes) ----------------
#define SM_B1    0          // 128 frags x 32 lanes x 16B = 64KB (rz: K=128,N=128)
#define SM_B2    65536      // 16KB (Wih_n: K=64,N=64)
#define SM_B3    81920      // 16KB (Whh_n)
#define SM_XA    98304      // float2[12][128] = 12KB
#define SM_WG3   110592     // float4[64] : {wg0, wg1, bg, 0}
#define SM_BIAS  111616     // float4[64] : {br, bz, bin, bhn}
#define SM_WFC   112640     // float[64]
#define SM_TOTAL 112896     // 2 CTAs per SM

__global__ void __launch_bounds__(256, 2)
k_fused(const float* __restrict__ x,
        const float* __restrict__ W_gcn, const float* __restrict__ b_gcn,
        const float* __restrict__ W_ih,  const float* __restrict__ W_hh,
        const float* __restrict__ b_ih,  const float* __restrict__ b_hh,
        const float* __restrict__ W_fc,  const float* __restrict__ b_fc,
        float* __restrict__ out) {
    extern __shared__ char smem[];
    const int tid  = threadIdx.x;
    const int wid  = tid >> 5;
    const int lane = tid & 31;
    const int gid  = lane >> 2;
    const int tig  = lane & 3;
    const int node0 = blockIdx.x * NPB;
    const int n0 = wid * 16 + gid;
    const int n1 = n0 + 8;

    // ---- build B fragments: ALL tf32 (rounded), column-permuted ----
    for (int i = tid; i < 6144; i += 256) {
        uint4 v;
        uint32_t dst;
        if (i < 4096) {                       // B1: rz, 8kt x 16nt
            int f = i >> 5, l = i & 31;
            int kt = f >> 4, nt = f & 15;
            int g = l >> 2, tg = l & 3;
            int j = 8 * nt + permj(g);
            const float* Wr = (kt < 4)
                ? (W_ih + j * 64 + 16 * kt + tg)
                : (W_hh + j * 64 + 16 * (kt - 4) + tg);
            v.x = tf32c(Wr[0]);
            v.y = tf32c(Wr[4]);
            v.z = tf32c(Wr[8]);
            v.w = tf32c(Wr[12]);
            dst = SM_B1 + (uint32_t)(f * 32 + l) * 16;
        } else if (i < 5120) {                // B2: Wih_n
            int ii = i - 4096;
            int f = ii >> 5, l = ii & 31;
            int kt = f >> 3, nt = f & 7;
            int g = l >> 2, tg = l & 3;
            int j = 8 * nt + permj(g);
            const float* Wr = W_ih + (128 + j) * 64 + 16 * kt + tg;
            v.x = tf32c(Wr[0]);
            v.y = tf32c(Wr[4]);
            v.z = tf32c(Wr[8]);
            v.w = tf32c(Wr[12]);
            dst = SM_B2 + (uint32_t)(f * 32 + l) * 16;
        } else {                              // B3: Whh_n
            int ii = i - 5120;
            int f = ii >> 5, l = ii & 31;
            int kt = f >> 3, nt = f & 7;
            int g = l >> 2, tg = l & 3;
            int j = 8 * nt + permj(g);
            const float* Wr = W_hh + (128 + j) * 64 + 16 * kt + tg;
            v.x = tf32c(Wr[0]);
            v.y = tf32c(Wr[4]);
            v.z = tf32c(Wr[8]);
            v.w = tf32c(Wr[12]);
            dst = SM_B3 + (uint32_t)(f * 32 + l) * 16;
        }
        *(uint4*)(smem + dst) = v;
    }

    // ---- XA: dinv*(agg_raw + dinv*x), layout float2[t][n] ----
    float* sXA = (float*)(smem + SM_XA);
    for (int i = tid; i < NPB * 24; i += 256) {
        int n = i / 24, cc = i - n * 24;
        int t = cc >> 1, c = cc & 1;
        int node = node0 + n;
        float v = 0.0f;
        if (node < NN) {
            float dv = g_dinv[node];
            v = dv * (g_agg[(size_t)node * 24 + cc] + dv * x[(size_t)node * 24 + cc]);
        }
        sXA[(t * 128 + n) * 2 + c] = v;
    }
    if (tid < 64) {
        float4* wg3 = (float4*)(smem + SM_WG3);
        wg3[tid] = make_float4(W_gcn[tid], W_gcn[64 + tid], b_gcn[tid], 0.0f);
        float4* bia = (float4*)(smem + SM_BIAS);
        bia[tid] = make_float4(b_ih[tid] + b_hh[tid],
                               b_ih[64 + tid] + b_hh[64 + tid],
                               b_ih[128 + tid], b_hh[128 + tid]);
        ((float*)(smem + SM_WFC))[tid] = W_fc[tid];
    }
    __syncthreads();

    const float4* sWG3  = (const float4*)(smem + SM_WG3);
    const float4* sBIAS = (const float4*)(smem + SM_BIAS);
    const float*  sWFC  = (const float*)(smem + SM_WFC);

    // ---- hidden state as fp32, directly in tf32 A-fragment layout ----
    // hA[m][0]=(rowA, k=8m+tig) [1]=(rowB, k=8m+tig) [2]=(rowA, +4) [3]=(rowB, +4)
    float hA[8][4];
#pragma unroll
    for (int m = 0; m < 8; m++)
#pragma unroll
        for (int q = 0; q < 4; q++) hA[m][q] = 0.0f;

#pragma unroll 1
    for (int t = 0; t < TT; t++) {
        float2 xaA = *(const float2*)(sXA + (t * 128 + n0) * 2);
        float2 xaB = *(const float2*)(sXA + (t * 128 + n1) * 2);

        // ---- S in fp32 A-fragment layout (fed raw; HW truncates to tf32) ----
        float sf[8][4];
#pragma unroll
        for (int m = 0; m < 8; m++) {
            int kb = 8 * m + tig;
            float4 w0 = sWG3[kb];
            float4 w4 = sWG3[kb + 4];
            sf[m][0] = fmaxf(fmaf(xaA.x, w0.x, fmaf(xaA.y, w0.y, w0.z)), 0.0f);
            sf[m][1] = fmaxf(fmaf(xaB.x, w0.x, fmaf(xaB.y, w0.y, w0.z)), 0.0f);
            sf[m][2] = fmaxf(fmaf(xaA.x, w4.x, fmaf(xaA.y, w4.y, w4.z)), 0.0f);
            sf[m][3] = fmaxf(fmaf(xaB.x, w4.x, fmaf(xaB.y, w4.y, w4.z)), 0.0f);
        }

        // ---- per-nt: accumulate gates, apply nonlinearity, write nhA ----
        float nhA[8][4];
#pragma unroll
        for (int nt = 0; nt < 8; nt++) {
            // D order: q0=(rowA,jt) q1=(rowA,jt+4) q2=(rowB,jt) q3=(rowB,jt+4)
            float aR[4] = {0, 0, 0, 0}, aZ[4] = {0, 0, 0, 0};
            float aI[4] = {0, 0, 0, 0}, aN[4] = {0, 0, 0, 0};
#pragma unroll
            for (int kt = 0; kt < 4; kt++) {
                uint4 bR = *(const uint4*)(smem + SM_B1 +
                             (uint32_t)((kt * 16 + nt) * 32 + lane) * 16);
                mma1688f(aR, sf[2 * kt],     bR.x, bR.y);
                mma1688f(aR, sf[2 * kt + 1], bR.z, bR.w);
                uint4 bZ = *(const uint4*)(smem + SM_B1 +
                             (uint32_t)((kt * 16 + nt + 8) * 32 + lane) * 16);
                mma1688f(aZ, sf[2 * kt],     bZ.x, bZ.y);
                mma1688f(aZ, sf[2 * kt + 1], bZ.z, bZ.w);
                uint4 b2 = *(const uint4*)(smem + SM_B2 +
                             (uint32_t)((kt * 8 + nt) * 32 + lane) * 16);
                mma1688f(aI, sf[2 * kt],     b2.x, b2.y);
                mma1688f(aI, sf[2 * kt + 1], b2.z, b2.w);
                uint4 b3 = *(const uint4*)(smem + SM_B3 +
                             (uint32_t)((kt * 8 + nt) * 32 + lane) * 16);
                mma1688f(aN, hA[2 * kt],     b3.x, b3.y);
                mma1688f(aN, hA[2 * kt + 1], b3.z, b3.w);
            }
#pragma unroll
            for (int kt = 0; kt < 4; kt++) {
                uint4 cR = *(const uint4*)(smem + SM_B1 +
                             (uint32_t)(((kt + 4) * 16 + nt) * 32 + lane) * 16);
                mma1688f(aR, hA[2 * kt],     cR.x, cR.y);
                mma1688f(aR, hA[2 * kt + 1], cR.z, cR.w);
                uint4 cZ = *(const uint4*)(smem + SM_B1 +
                             (uint32_t)(((kt + 4) * 16 + nt + 8) * 32 + lane) * 16);
                mma1688f(aZ, hA[2 * kt],     cZ.x, cZ.y);
                mma1688f(aZ, hA[2 * kt + 1], cZ.z, cZ.w);
            }
            int jb = 8 * nt + tig;
            float4 bj0 = sBIAS[jb];        // j = tig
            float4 bj1 = sBIAS[jb + 4];    // j = tig+4
            // q0: rowA, jt  (hold = hA[nt][0] -> nhA[nt][0])
            {
                float r = fsigmoid(aR[0] + bj0.x);
                float z = fsigmoid(aZ[0] + bj0.y);
                float nn = ftanh(fmaf(r, aN[0] + bj0.w, aI[0] + bj0.z));
                nhA[nt][0] = fmaf(z, hA[nt][0] - nn, nn);
            }
            // q1: rowA, jt+4 (hold = hA[nt][2] -> nhA[nt][2])
            {
                float r = fsigmoid(aR[1] + bj1.x);
                float z = fsigmoid(aZ[1] + bj1.y);
                float nn = ftanh(fmaf(r, aN[1] + bj1.w, aI[1] + bj1.z));
                nhA[nt][2] = fmaf(z, hA[nt][2] - nn, nn);
            }
            // q2: rowB, jt  (hold = hA[nt][1] -> nhA[nt][1])
            {
                float r = fsigmoid(aR[2] + bj0.x);
                float z = fsigmoid(aZ[2] + bj0.y);
                float nn = ftanh(fmaf(r, aN[2] + bj0.w, aI[2] + bj0.z));
                nhA[nt][1] = fmaf(z, hA[nt][1] - nn, nn);
            }
            // q3: rowB, jt+4 (hold = hA[nt][3] -> nhA[nt][3])
            {
                float r = fsigmoid(aR[3] + bj1.x);
                float z = fsigmoid(aZ[3] + bj1.y);
                float nn = ftanh(fmaf(r, aN[3] + bj1.w, aI[3] + bj1.z));
                nhA[nt][3] = fmaf(z, hA[nt][3] - nn, nn);
            }
        }
#pragma unroll
        for (int m = 0; m < 8; m++)
#pragma unroll
            for (int q = 0; q < 4; q++) hA[m][q] = nhA[m][q];
    }

    // ---- FC readout ----
    float pA = 0.0f, pB = 0.0f;
#pragma unroll
    for (int nt = 0; nt < 8; nt++) {
        int jb = 8 * nt + tig;
        float w0 = sWFC[jb], w1 = sWFC[jb + 4];
        pA = fmaf(hA[nt][0], w0, fmaf(hA[nt][2], w1, pA));
        pB = fmaf(hA[nt][1], w0, fmaf(hA[nt][3], w1, pB));
    }
    pA += __shfl_xor_sync(0xFFFFFFFF, pA, 1);
    pA += __shfl_xor_sync(0xFFFFFFFF, pA, 2);
    pB += __shfl_xor_sync(0xFFFFFFFF, pB, 1);
    pB += __shfl_xor_sync(0xFFFFFFFF, pB, 2);
    if (tig == 0) {
        float bfc = b_fc[0];
        int nodeA = node0 + n0;
        int nodeB = node0 + n1;
        if (nodeA < NN) out[nodeA] = pA + bfc;
        if (nodeB < NN) out[nodeB] = pB + bfc;
    }
}

// ---------------- launch ----------------
extern "C" void kernel_launch(void* const* d_in, const int* in_sizes, int n_in,
                              void* d_out, int out_size) {
    const float* x     = (const float*)d_in[0];
    const int*   ei32  = (const int*)d_in[1];
    const float* W_gcn = (const float*)d_in[2];
    const float* b_gcn = (const float*)d_in[3];
    const float* W_ih  = (const float*)d_in[4];
    const float* W_hh  = (const float*)d_in[5];
    const float* b_ih  = (const float*)d_in[6];
    const float* b_hh  = (const float*)d_in[7];
    const float* W_fc  = (const float*)d_in[8];
    const float* b_fc  = (const float*)d_in[9];
    float* out = (float*)d_out;

    static bool attr_set = false;
    if (!attr_set) {
        cudaFuncSetAttribute(k_fused, cudaFuncAttributeMaxDynamicSharedMemorySize,
                             SM_TOTAL);
        attr_set = true;
    }

    k_initprobe<<<SCAN_BLOCKS, 256>>>(ei32);
    k_count<<<(NE + 255) / 256, 256>>>(ei32);
    k_scan1<<<SCAN_BLOCKS, 256>>>();
    k_scan2<<<1, 256>>>();
    k_scan3<<<SCAN_BLOCKS, 256>>>();
    k_fill<<<(NE + 255) / 256, 256>>>(ei32);
    k_gather<<<(NN * 32 + 255) / 256, 256>>>(x);
    k_fused<<<(NN + NPB - 1) / NPB, 256, SM_TOTAL>>>(
        x, W_gcn, b_gcn, W_ih, W_hh, b_ih, b_hh, W_fc, b_fc, out);
}